// round 9
// baseline (speedup 1.0000x reference)
#include <cuda_runtime.h>

// ---------------------------------------------------------------------------
// MS-SSIM, 4 levels, 11-tap Gaussian (sigma=1.5), VALID padding.
// X, Y: [16, 3, 512, 512] fp32. Output: 16 fp32 (1 - ms_ssim per batch).
//
// R9: R8 fork/join graph + (a) batched row loads (MLP=11) in the tap loop,
// (b) low-priority side streams so ssim0 wins SM dispatch under contention.
// ---------------------------------------------------------------------------

#define KW 11
#define NB 16
#define NC 3

__device__ double g_acc[4 * NB];
__device__ float g_X1[NB * NC * 256 * 256];
__device__ float g_Y1[NB * NC * 256 * 256];
__device__ float g_X2[NB * NC * 128 * 128];
__device__ float g_Y2[NB * NC * 128 * 128];
__device__ float g_X3[NB * NC * 64 * 64];
__device__ float g_Y3[NB * NC * 64 * 64];

typedef unsigned long long ull;

__device__ __forceinline__ ull pk2(float lo, float hi) {
    ull r; asm("mov.b64 %0,{%1,%2};" : "=l"(r) : "f"(lo), "f"(hi)); return r;
}
__device__ __forceinline__ void up2(ull v, float& lo, float& hi) {
    asm("mov.b64 {%0,%1},%2;" : "=f"(lo), "=f"(hi) : "l"(v));
}
__device__ __forceinline__ ull fma2(ull a, ull b, ull c) {
    ull d; asm("fma.rn.f32x2 %0,%1,%2,%3;" : "=l"(d) : "l"(a), "l"(b), "l"(c));
    return d;
}
__device__ __forceinline__ ull mul2(ull a, ull b) {
    ull d; asm("mul.rn.f32x2 %0,%1,%2;" : "=l"(d) : "l"(a), "l"(b));
    return d;
}

__global__ void zero_acc_kernel() {
    int i = threadIdx.x;
    if (i < 4 * NB) g_acc[i] = 0.0;
}

// ---------------------------------------------------------------------------
// Hierarchical pool: 32x32 patch per block -> 16x16 L1, 8x8 L2, 4x4 L3.
// ---------------------------------------------------------------------------
__global__ __launch_bounds__(256) void pool_all_kernel(
    const float* __restrict__ X, const float* __restrict__ Y)
{
    __shared__ float2 s1[16][17];
    __shared__ float2 s2[8][9];

    const int plane = blockIdx.x >> 8;
    const int patch = blockIdx.x & 255;
    const int px = patch & 15, py = patch >> 4;
    const int tid = threadIdx.x;
    const int tx = tid & 15, ty = tid >> 4;

    const float* __restrict__ Xp = X + (size_t)plane * 512 * 512;
    const float* __restrict__ Yp = Y + (size_t)plane * 512 * 512;

    const int gy = py * 32 + 2 * ty;
    const int gx = px * 32 + 2 * tx;
    const int o0 = gy * 512 + gx;

    float2 xa = *(const float2*)(Xp + o0);
    float2 xb = *(const float2*)(Xp + o0 + 512);
    float2 ya = *(const float2*)(Yp + o0);
    float2 yb = *(const float2*)(Yp + o0 + 512);
    float xv = 0.25f * ((xa.x + xa.y) + (xb.x + xb.y));
    float yv = 0.25f * ((ya.x + ya.y) + (yb.x + yb.y));

    g_X1[(size_t)plane * 256 * 256 + (py * 16 + ty) * 256 + (px * 16 + tx)] = xv;
    g_Y1[(size_t)plane * 256 * 256 + (py * 16 + ty) * 256 + (px * 16 + tx)] = yv;
    s1[ty][tx] = make_float2(xv, yv);
    __syncthreads();

    if (tid < 64) {
        int t2x = tid & 7, t2y = tid >> 3;
        float2 a = s1[2 * t2y][2 * t2x];
        float2 b = s1[2 * t2y][2 * t2x + 1];
        float2 c = s1[2 * t2y + 1][2 * t2x];
        float2 d = s1[2 * t2y + 1][2 * t2x + 1];
        float x2 = 0.25f * ((a.x + b.x) + (c.x + d.x));
        float y2 = 0.25f * ((a.y + b.y) + (c.y + d.y));
        g_X2[(size_t)plane * 128 * 128 + (py * 8 + t2y) * 128 + (px * 8 + t2x)] = x2;
        g_Y2[(size_t)plane * 128 * 128 + (py * 8 + t2y) * 128 + (px * 8 + t2x)] = y2;
        s2[t2y][t2x] = make_float2(x2, y2);
    }
    __syncthreads();

    if (tid < 16) {
        int t3x = tid & 3, t3y = tid >> 2;
        float2 a = s2[2 * t3y][2 * t3x];
        float2 b = s2[2 * t3y][2 * t3x + 1];
        float2 c = s2[2 * t3y + 1][2 * t3x];
        float2 d = s2[2 * t3y + 1][2 * t3x + 1];
        float x3 = 0.25f * ((a.x + b.x) + (c.x + d.x));
        float y3 = 0.25f * ((a.y + b.y) + (c.y + d.y));
        g_X3[(size_t)plane * 64 * 64 + (py * 4 + t3y) * 64 + (px * 4 + t3x)] = x3;
        g_Y3[(size_t)plane * 64 * 64 + (py * 4 + t3y) * 64 + (px * 4 + t3x)] = y3;
    }
}

// ---------------------------------------------------------------------------
// Per-level SSIM kernel. Batched row loads (MLP=11) before the tap chain.
// Grid: (tilesX*tilesY, NC, NB), block: TW_ threads.
// ---------------------------------------------------------------------------
template<int TW_, int TH_, bool LAST>
__global__ __launch_bounds__(TW_) void ssim_level_kernel(
    const float* __restrict__ X, const float* __restrict__ Y,
    int H, int W, int outH, int outW, int tilesX, int level)
{
    constexpr int IH_  = TH_ + KW - 1;
    constexpr int IW_  = TW_ + KW - 1;
    constexpr int IWP_ = TW_ + 12;
    constexpr int NWARP = TW_ / 32;

    __shared__ float2 sxy[IH_][IWP_];
    __shared__ float red[NWARP];

    const int b = blockIdx.z;
    const int c = blockIdx.y;
    const int tile = blockIdx.x;
    const int tx = tile % tilesX;
    const int ty = tile / tilesX;
    const int ix0 = tx * TW_;
    const int iy0 = ty * TH_;
    const int tid = threadIdx.x;

    const size_t plane = (size_t)(b * NC + c) * H * W;
    const float* __restrict__ Xi = X + plane;
    const float* __restrict__ Yi = Y + plane;

    #pragma unroll 4
    for (int i = tid; i < IH_ * IW_; i += TW_) {
        int r  = i / IW_;
        int cc = i - r * IW_;
        int gy = min(iy0 + r,  H - 1);
        int gx = min(ix0 + cc, W - 1);
        int gi = gy * W + gx;
        sxy[r][cc] = make_float2(Xi[gi], Yi[gi]);
    }
    __syncthreads();

    const float G[KW] = {
        0.00102838f, 0.00759875f, 0.03600077f, 0.10936069f, 0.21300553f,
        0.26601174f,
        0.21300553f, 0.10936069f, 0.03600077f, 0.00759875f, 0.00102838f
    };
    const float C1 = 1e-4f;
    const float C2 = 9e-4f;

    ull   r01[KW];
    ull   r23[KW];
    float r4[KW];

    const int lx = tid;
    const int ox = ix0 + lx;
    const bool colOK = (ox < outW);
    float local = 0.f;

    #pragma unroll
    for (int r = 0; r < IH_; r++) {
        const ull* __restrict__ row =
            reinterpret_cast<const ull*>(&sxy[r][lx]);

        // Batched loads: 11 independent LDS.64 issued before any dependent FMA.
        ull v[KW];
        #pragma unroll
        for (int k = 0; k < KW; k++) v[k] = row[k];

        ull s01, s23; float s4;
        {
            ull gg = pk2(G[0], G[0]);
            s01 = mul2(gg, v[0]);
            ull t = mul2(gg, v[0]);
            s23 = mul2(t, v[0]);
            float xv, yv, tl, th;
            up2(v[0], xv, yv); up2(t, tl, th);
            s4 = tl * yv;
            (void)xv; (void)th;
        }
        #pragma unroll
        for (int k = 1; k < KW; k++) {
            ull gg = pk2(G[k], G[k]);
            s01 = fma2(gg, v[k], s01);
            ull t = mul2(gg, v[k]);
            s23 = fma2(t, v[k], s23);
            float xv, yv, tl, th;
            up2(v[k], xv, yv); up2(t, tl, th);
            s4 = fmaf(tl, yv, s4);
            (void)xv; (void)th;
        }
        r01[r % KW] = s01;
        r23[r % KW] = s23;
        r4[r % KW]  = s4;

        if (r >= KW - 1) {
            const int orow = r - (KW - 1);
            ull m01, m23; float m4;
            {
                int idx = orow % KW;
                ull gg = pk2(G[0], G[0]);
                m01 = mul2(gg, r01[idx]);
                m23 = mul2(gg, r23[idx]);
                m4  = G[0] * r4[idx];
            }
            #pragma unroll
            for (int k = 1; k < KW; k++) {
                int idx = (orow + k) % KW;
                ull gg = pk2(G[k], G[k]);
                m01 = fma2(gg, r01[idx], m01);
                m23 = fma2(gg, r23[idx], m23);
                m4  = fmaf(G[k], r4[idx], m4);
            }
            int oy = iy0 + orow;
            if (colOK && oy < outH) {
                float mu1, mu2, xx, yy;
                up2(m01, mu1, mu2);
                up2(m23, xx, yy);
                float s1q = xx - mu1 * mu1;
                float s2q = yy - mu2 * mu2;
                float s12 = m4 - mu1 * mu2;
                float cs = __fdividef(2.f * s12 + C2, s1q + s2q + C2);
                cs = fmaxf(cs, 0.f);
                if (LAST) {
                    float lum = __fdividef(2.f * mu1 * mu2 + C1,
                                           mu1 * mu1 + mu2 * mu2 + C1);
                    local = fmaf(lum, cs, local);
                } else {
                    local += cs;
                }
            }
        }
    }

    #pragma unroll
    for (int s = 16; s > 0; s >>= 1)
        local += __shfl_down_sync(0xffffffffu, local, s);
    if ((tid & 31) == 0) red[tid >> 5] = local;
    __syncthreads();
    if (tid == 0) {
        float t = 0.f;
        #pragma unroll
        for (int w = 0; w < NWARP; w++) t += red[w];
        atomicAdd(&g_acc[level * NB + b], (double)t);
    }
}

__global__ void finalize_kernel(float* __restrict__ out) {
    int b = threadIdx.x;
    if (b >= NB) return;
    const double counts[4] = {
        3.0 * 502.0 * 502.0,
        3.0 * 246.0 * 246.0,
        3.0 * 118.0 * 118.0,
        3.0 * 54.0  * 54.0
    };
    const double wraw[4] = {0.0448, 0.2856, 0.3001, 0.2363};
    const double wsum = 0.0448 + 0.2856 + 0.3001 + 0.2363;
    double s = 0.0;
    #pragma unroll
    for (int l = 0; l < 4; l++) {
        double v = g_acc[l * NB + b] / counts[l];
        v = v > 1e-8 ? v : 1e-8;
        s += (wraw[l] / wsum) * log(v);
    }
    out[b] = (float)(1.0 - exp(s));
}

// ---------------------------------------------------------------------------
// Streams (LOWEST priority for branch B) + events, created at static init.
// ---------------------------------------------------------------------------
struct GraphResources {
    cudaStream_t s2, s3, s4;
    cudaEvent_t eFork, ePool, eJ1, eJ2, eJ3;
    GraphResources() {
        int loPri = 0, hiPri = 0;
        cudaDeviceGetStreamPriorityRange(&loPri, &hiPri);
        // loPri is the numerically-largest (least urgent) priority.
        cudaStreamCreateWithPriority(&s2, cudaStreamNonBlocking, loPri);
        cudaStreamCreateWithPriority(&s3, cudaStreamNonBlocking, loPri);
        cudaStreamCreateWithPriority(&s4, cudaStreamNonBlocking, loPri);
        cudaEventCreateWithFlags(&eFork, cudaEventDisableTiming);
        cudaEventCreateWithFlags(&ePool, cudaEventDisableTiming);
        cudaEventCreateWithFlags(&eJ1, cudaEventDisableTiming);
        cudaEventCreateWithFlags(&eJ2, cudaEventDisableTiming);
        cudaEventCreateWithFlags(&eJ3, cudaEventDisableTiming);
    }
};
static GraphResources g_res;

extern "C" void kernel_launch(void* const* d_in, const int* in_sizes, int n_in,
                              void* d_out, int out_size)
{
    const float* X = (const float*)d_in[0];
    const float* Y = (const float*)d_in[1];
    float* out = (float*)d_out;
    (void)in_sizes; (void)n_in; (void)out_size;

    static float *pX1 = nullptr, *pY1 = nullptr, *pX2 = nullptr, *pY2 = nullptr,
                 *pX3 = nullptr, *pY3 = nullptr;
    if (!pX1) {
        cudaGetSymbolAddress((void**)&pX1, g_X1);
        cudaGetSymbolAddress((void**)&pY1, g_Y1);
        cudaGetSymbolAddress((void**)&pX2, g_X2);
        cudaGetSymbolAddress((void**)&pY2, g_Y2);
        cudaGetSymbolAddress((void**)&pX3, g_X3);
        cudaGetSymbolAddress((void**)&pY3, g_Y3);
    }

    // ---- s0: zero, fork event ----
    zero_acc_kernel<<<1, 64>>>();
    cudaEventRecord(g_res.eFork, 0);

    // ---- s0: ssim0 — created first, default (higher) priority ----
    {
        dim3 grid(4 * 16, NC, NB);    // L0: 128x32 tiles over 502x502
        ssim_level_kernel<128, 32, false><<<grid, 128>>>(
            X, Y, 512, 512, 502, 502, 4, 0);
    }

    // ---- branch B (low priority): pool, then L1/L2/L3 concurrently ----
    cudaStreamWaitEvent(g_res.s2, g_res.eFork, 0);
    pool_all_kernel<<<NB * NC * 256, 256, 0, g_res.s2>>>(X, Y);
    cudaEventRecord(g_res.ePool, g_res.s2);
    cudaStreamWaitEvent(g_res.s3, g_res.ePool, 0);
    cudaStreamWaitEvent(g_res.s4, g_res.ePool, 0);

    {
        dim3 grid(2 * 8, NC, NB);     // L1: 128x32 tiles over 246x246
        ssim_level_kernel<128, 32, false><<<grid, 128, 0, g_res.s2>>>(
            pX1, pY1, 256, 256, 246, 246, 2, 1);
    }
    {
        dim3 grid(2 * 8, NC, NB);     // L2: 64x16 tiles over 118x118
        ssim_level_kernel<64, 16, false><<<grid, 64, 0, g_res.s3>>>(
            pX2, pY2, 128, 128, 118, 118, 2, 2);
    }
    {
        dim3 grid(1 * 4, NC, NB);     // L3: 64x16 tiles over 54x54
        ssim_level_kernel<64, 16, true><<<grid, 64, 0, g_res.s4>>>(
            pX3, pY3, 64, 64, 54, 54, 1, 3);
    }
    cudaEventRecord(g_res.eJ1, g_res.s2);
    cudaEventRecord(g_res.eJ2, g_res.s3);
    cudaEventRecord(g_res.eJ3, g_res.s4);

    // ---- join + finalize on s0 ----
    cudaStreamWaitEvent(0, g_res.eJ1, 0);
    cudaStreamWaitEvent(0, g_res.eJ2, 0);
    cudaStreamWaitEvent(0, g_res.eJ3, 0);
    finalize_kernel<<<1, 32>>>(out);
}